// round 5
// baseline (speedup 1.0000x reference)
#include <cuda_runtime.h>
#include <cuda_bf16.h>

// Problem constants (fixed by the reference): N=512, B=256, F=400, D=14, K=2
#define NN 512
#define BB 256
#define FF 400
#define DD 14
#define KK 2
#define PIX (DD * DD)                 // 196 pixels per (b,f)
#define NTILES (BB * FF)              // 102400 (b,f) tiles
#define TPW 4                         // tiles per warp (8 lanes per tile)
#define NWARPS (NTILES / TPW)         // 25600 warps
#define LOG2E 1.4426950408889634074f
#define INV2PI 0.15915494309189533577f

// Guaranteed single-MUFU ops regardless of harness compile flags.
__device__ __forceinline__ float ex2f_fast(float x) {
    float r; asm("ex2.approx.ftz.f32 %0, %1;" : "=f"(r) : "f"(x)); return r;
}
__device__ __forceinline__ float rcpf_fast(float x) {
    float r; asm("rcp.approx.ftz.f32 %0, %1;" : "=f"(r) : "f"(x)); return r;
}

// Warp layout: 4 tiles per warp; group g = lane>>3 handles tile warp*4+g,
// lane q = lane&7 within the group.
//   Lane q (q<7) owns column pair j = 2q, 2q+1 of ALL 14 rows; lane q=7 is a spare.
//   The x-axis Gaussian factor follows a row-stride-1 multiplicative recurrence:
//     g(r+1) = g(r)*m(r),  m(r+1) = m(r)*s,  m = exp2(a(2d+1)),  s = exp2(2a)
//   with the spot coefficient mask*h/(2*pi*w^2) folded into g's initial value
//   (masked spot -> c=0 -> g==0 at every row). 8 lanes per tile means the
//   per-tile parameter prologue is amortized 2x better than 16 lanes/tile.
__global__ __launch_bounds__(256) void gaussian_spot_kernel(
    const int*          __restrict__ batch_idx,   // (B,)
    const uint2*        __restrict__ m_mask,      // (B,F,K) 32-bit words; nonzero == true
    const float2*       __restrict__ height,      // (B,F,K)
    const float2*       __restrict__ width,       // (B,F,K)
    const float2*       __restrict__ x0,          // (B,F,K)
    const float2*       __restrict__ y0,          // (B,F,K)
    const float*        __restrict__ background,  // (B,F)
    const float2*       __restrict__ target_locs, // (N,F,2)
    float*              __restrict__ out)         // (B,F,D,D)
{
    const int warp = (blockIdx.x * blockDim.x + threadIdx.x) >> 5;
    const int lane = threadIdx.x & 31;
    const int q    = lane & 7;                 // column-pair index within tile
    const int grp  = lane >> 3;                // tile group 0..3

    const int bf = warp * TPW + grp;           // this lane's tile (grid is exact)
    const int b  = bf / FF;
    const int f  = bf - b * FF;

    // ---- per-tile parameters (uniform within each 8-lane group) ----
    const int    n   = batch_idx[b];
    const float2 tl  = target_locs[n * FF + f];
    const float  bg  = background[bf];

    const uint2  mm = m_mask[bf];
    const float2 hh = height[bf];
    const float2 ww = width[bf];
    const float2 xx = x0[bf];
    const float2 yy = y0[bf];

    // spot 0
    const float h0   = (mm.x != 0u) ? hh.x : 0.0f;
    const float iw20 = rcpf_fast(ww.x * ww.x);
    const float a0   = (-0.5f * LOG2E) * iw20;        // exp2-scaled exponent coeff
    const float c0   = h0 * iw20 * INV2PI;
    const float cx0  = tl.x + xx.x;
    const float cy0  = tl.y + yy.x;
    // spot 1
    const float h1   = (mm.y != 0u) ? hh.y : 0.0f;
    const float iw21 = rcpf_fast(ww.y * ww.y);
    const float a1   = (-0.5f * LOG2E) * iw21;
    const float c1   = h1 * iw21 * INV2PI;
    const float cx1  = tl.x + xx.y;
    const float cy1  = tl.y + yy.y;

    // ---- x-axis recurrence state, starting at row 0, stride 1 ----
    const float d0 = -cx0;
    const float d1 = -cx1;
    float g0 = c0 * ex2f_fast(a0 * d0 * d0);   // coeff folded in
    float m0 = ex2f_fast(a0 * (2.0f * d0 + 1.0f));
    const float sA = ex2f_fast(2.0f * a0);
    float g1 = c1 * ex2f_fast(a1 * d1 * d1);
    float m1 = ex2f_fast(a1 * (2.0f * d1 + 1.0f));
    const float sB = ex2f_fast(2.0f * a1);

    // ---- y entries for columns 2q, 2q+1 (fixed per lane; q=7 is spare) ----
    const float py0 = (float)(2 * q);
    const float py1 = py0 + 1.0f;
    const float e00 = py0 - cy0, e01 = py1 - cy0;
    const float e10 = py0 - cy1, e11 = py1 - cy1;
    const float ya_e = ex2f_fast(a0 * e00 * e00);
    const float ya_o = ex2f_fast(a0 * e01 * e01);
    const float yb_e = ex2f_fast(a1 * e10 * e10);
    const float yb_o = ex2f_fast(a1 * e11 * e11);

    // ---- 14 row iterations; no shuffles ----
    float2* o = (float2*)(out + (size_t)bf * PIX) + q;   // row 0, colpair q
    const bool active = (q < 7);

#pragma unroll
    for (int it = 0; it < DD; ++it) {
        float2 v;
        v.x = fmaf(g0, ya_e, fmaf(g1, yb_e, bg));
        v.y = fmaf(g0, ya_o, fmaf(g1, yb_o, bg));
        if (active) __stcs(&o[it * 7], v);     // streaming store, next row = 7 float2
        g0 *= m0;  m0 *= sA;                   // row += 1
        g1 *= m1;  m1 *= sB;
    }
}

extern "C" void kernel_launch(void* const* d_in, const int* in_sizes, int n_in,
                              void* d_out, int out_size) {
    (void)in_sizes; (void)n_in; (void)out_size;
    const int*    batch_idx   = (const int*)d_in[0];
    const uint2*  m_mask      = (const uint2*)d_in[1];
    const float2* height      = (const float2*)d_in[2];
    const float2* width       = (const float2*)d_in[3];
    const float2* x0          = (const float2*)d_in[4];
    const float2* y0          = (const float2*)d_in[5];
    const float*  background  = (const float*)d_in[6];
    const float2* target_locs = (const float2*)d_in[7];
    // d_in[8] = pixel_pos (meshgrid) — implicit in the kernel, unused.
    float* out = (float*)d_out;

    const int threads = 256;                      // 8 warps/block, 32 tiles/block
    const int blocks  = (NWARPS * 32) / threads;  // 3200, exact
    gaussian_spot_kernel<<<blocks, threads>>>(batch_idx, m_mask, height, width,
                                              x0, y0, background, target_locs, out);
}